// round 10
// baseline (speedup 1.0000x reference)
#include <cuda_runtime.h>
#include <math.h>

// Problem constants (fixed by the reference)
#define HH 512
#define WW 512
#define HP 64
#define WP 2048
#define BB 4
#define CC 64
#define HW (HH * WW)          // 262144 cart pixels per plane
#define PLANE (HP * WP)       // 131072 polar elements per plane

#define PW 136                // polar patch width  (floats)
#define PH 10                 // polar patch height (rows)
#define GC 4                  // channels staged per group

// Block = 256 threads, 32(x) x 8(y) cart tile, LINEAR lane map (warp = one
// cart row -> coalesced stores). Gathers read from an smem polar patch that
// the block stages cooperatively (coalesced) per 4-channel group; blocks
// whose polar support exceeds the patch (center disk + phi-seam, ~6%) take a
// direct-gather fallback.
__global__ void __launch_bounds__(256, 8)
k_fused(const float* __restrict__ polar,
        const float* __restrict__ ref,
        float*       __restrict__ out) {
    __shared__ float sp[GC * PH * PW];     // 21.76 KB patch
    __shared__ int   sred[32];             // per-warp partial min/max

    const int tid  = threadIdx.x;
    const int lane = tid & 31;
    const int warp = tid >> 5;
    const int tx   = tid & 31;             // linear: warp = one cart row
    const int ty   = tid >> 5;

    const int x = (blockIdx.x << 5) + tx;
    const int y = (blockIdx.y << 3) + ty;
    const int b = blockIdx.z;

    // ---- analytic map (mask chain bitwise == numpy, proven R6/R7) ----
    const float c1  = 362.03867196751236f;           // f32(256*sqrt(2))
    const float PIf = 3.14159265358979323846f;       // f32(np.pi)

    const float yyc = ((float)y - 256.0f) + 0.5f;
    const float xxc = ((float)x - 256.0f) + 0.5f;

    float d2    = __fadd_rn(__fmul_rn(xxc, xxc), __fmul_rn(yyc, yyc));
    float depth = __fsqrt_rn(d2);
    float index_y = __fsub_rn(__fmul_rn(__fdiv_rn(depth, c1), 67.0f), 3.0f);
    const bool mapped = (index_y > 0.0f);

    float phi     = PIf - atan2f(yyc, xxc);
    float index_x = phi / PIf / 2.0f * (float)WP;
    float gx  = index_x / (float)WP * 2.0f - 1.0f;
    float gyv = -(index_y / (float)HP * 2.0f - 1.0f);
    float ixf = (gx  + 1.0f) * ((WP - 1) * 0.5f);
    float iyf = (gyv + 1.0f) * ((HP - 1) * 0.5f);

    float x0f = floorf(ixf);
    float y0f = floorf(iyf);
    float wx  = ixf - x0f;
    float wy  = iyf - y0f;
    int   x0  = (int)x0f;
    int   y0  = (int)y0f;

    y0 = min(max(y0, 0), HP - 2);
    if (x0 < 0)      { x0 = 0;      wx = 0.0f; }
    if (x0 > WP - 2) { x0 = WP - 2; wx = 1.0f; }

    float wxm = 1.0f - wx, wym = 1.0f - wy;
    const float w00 = wxm * wym;
    const float w01 = wx  * wym;
    const float w10 = wxm * wy;
    const float w11 = wx  * wy;

    // ---- block-wide min/max of (x0, y0) ----
    int xmn = x0, xmx = x0, ymn = y0, ymx = y0;
    #pragma unroll
    for (int o = 16; o; o >>= 1) {
        xmn = min(xmn, __shfl_xor_sync(0xffffffffu, xmn, o));
        xmx = max(xmx, __shfl_xor_sync(0xffffffffu, xmx, o));
        ymn = min(ymn, __shfl_xor_sync(0xffffffffu, ymn, o));
        ymx = max(ymx, __shfl_xor_sync(0xffffffffu, ymx, o));
    }
    if (lane == 0) {
        sred[warp]      = xmn;
        sred[8 + warp]  = xmx;
        sred[16 + warp] = ymn;
        sred[24 + warp] = ymx;
    }
    __syncthreads();
    xmn = sred[0]; xmx = sred[8]; ymn = sred[16]; ymx = sred[24];
    #pragma unroll
    for (int i = 1; i < 8; ++i) {
        xmn = min(xmn, sred[i]);
        xmx = max(xmx, sred[8 + i]);
        ymn = min(ymn, sred[16 + i]);
        ymx = max(ymx, sred[24 + i]);
    }
    const int W     = xmx + 2 - xmn;   // columns needed (incl. +1 tap)
    const int nrows = ymx + 2 - ymn;   // rows needed

    const size_t obase = ((size_t)b * CC) * HW + (size_t)y * WW + x;

    if (W <= PW && nrows <= PH) {
        // ================= main path: smem patch gather =================
        // (all pixels provably mapped here: unmapped => r<16.3 => W>>PW)
        const float* pb   = polar + (size_t)b * CC * PLANE;
        const size_t gofs = (size_t)ymn * WP + xmn;
        const int    lb   = (y0 - ymn) * PW + (x0 - xmn);

        for (int g = 0; g < CC / GC; ++g) {
            __syncthreads();               // sp reuse guard
            const float* ps = pb + (size_t)(g * GC) * PLANE + gofs;
            for (int py = 0; py < nrows; ++py) {
                #pragma unroll
                for (int c = 0; c < GC; ++c) {
                    int px = tid;
                    if (px < W)
                        sp[(c * PH + py) * PW + px] =
                            __ldg(ps + (size_t)c * PLANE + py * WP + px);
                }
            }
            __syncthreads();

            float* o = out + obase + (size_t)(g * GC) * HW;
            #pragma unroll
            for (int c = 0; c < GC; ++c) {
                const float* s = sp + (c * PH) * PW + lb;
                float v = s[0]  * w00 + s[1]      * w01
                        + s[PW] * w10 + s[PW + 1] * w11;
                __stcs(o + (size_t)c * HW, v);
            }
        }
    } else {
        // ============== fallback: direct gather (center/seam) ==========
        float* o = out + obase;
        if (mapped) {
            const float* pp = polar + (size_t)b * CC * PLANE
                            + (size_t)y0 * WP + x0;
            #pragma unroll 4
            for (int c = 0; c < CC; ++c) {
                float v00 = __ldg(pp);
                float v01 = __ldg(pp + 1);
                float v10 = __ldg(pp + WP);
                float v11 = __ldg(pp + WP + 1);
                __stcs(o, v00 * w00 + v01 * w01 + v10 * w10 + v11 * w11);
                pp += PLANE;
                o  += HW;
            }
        } else {
            const float* r = ref + obase;
            #pragma unroll 8
            for (int c = 0; c < CC; ++c) {
                __stcs(o, __ldg(r));
                r += HW;
                o += HW;
            }
        }
    }
}

extern "C" void kernel_launch(void* const* d_in, const int* in_sizes, int n_in,
                              void* d_out, int out_size) {
    const float* polar = (const float*)d_in[0];   // [B,C,HP,WP]
    const float* ref   = (const float*)d_in[1];   // [B,C,H,W]
    float*       out   = (float*)d_out;           // [B,C,H,W]

    dim3 grid(WW / 32, HH / 8, BB);   // (16, 64, 4) = 4096 blocks
    k_fused<<<grid, 256>>>(polar, ref, out);
}

// round 12
// speedup vs baseline: 1.0943x; 1.0943x over previous
#include <cuda_runtime.h>
#include <math.h>

// Problem constants (fixed by the reference)
#define HH 512
#define WW 512
#define HP 64
#define WP 2048
#define BB 4
#define CC 64
#define HW (HH * WW)          // 262144 cart pixels per plane
#define PLANE (HP * WP)       // 131072 polar elements per plane

#define PW 136                // polar patch width  (floats per row)
#define PH 9                  // polar patch height (rows)
#define GC 4                  // channels staged per group (2 float2 pairs)
#define NGRP (CC / GC)        // 16 groups

// Block = 256 threads, 32(x) x 8(y) cart tile, LINEAR lane map (warp = one
// cart row -> naturally coalesced stores). Main path stages a rectangular
// polar patch (channel-PAIR interleaved, float2) into smem with flattened,
// fully-coalesced cooperative loads, then bilinear-gathers via LDS.64
// (one instruction feeds 2 channels). Blocks whose polar support exceeds
// the patch (center disk + phi seam, ~8%) take the direct-gather fallback.
__global__ void __launch_bounds__(256, 8)
k_fused(const float* __restrict__ polar,
        const float* __restrict__ ref,
        float*       __restrict__ out) {
    __shared__ float2 sp[(GC / 2) * PH * PW];   // 2 pairs x 9 x 136 = 19.6 KB
    __shared__ int    sred[32];

    const int tid  = threadIdx.x;
    const int lane = tid & 31;
    const int warp = tid >> 5;
    const int tx   = tid & 31;     // linear lane map
    const int ty   = tid >> 5;

    const int x = (blockIdx.x << 5) + tx;
    const int y = (blockIdx.y << 3) + ty;
    const int b = blockIdx.z;

    // ---- analytic map (mask chain bitwise == numpy, proven R6/R7) ----
    const float c1  = 362.03867196751236f;       // f32(256*sqrt(2))
    const float PIf = 3.14159265358979323846f;   // f32(np.pi)

    const float yyc = ((float)y - 256.0f) + 0.5f;
    const float xxc = ((float)x - 256.0f) + 0.5f;

    float d2    = __fadd_rn(__fmul_rn(xxc, xxc), __fmul_rn(yyc, yyc));
    float depth = __fsqrt_rn(d2);
    float index_y = __fsub_rn(__fmul_rn(__fdiv_rn(depth, c1), 67.0f), 3.0f);
    const bool mapped = (index_y > 0.0f);

    float phi     = PIf - atan2f(yyc, xxc);
    float index_x = phi / PIf / 2.0f * (float)WP;
    float gx  = index_x / (float)WP * 2.0f - 1.0f;
    float gyv = -(index_y / (float)HP * 2.0f - 1.0f);
    float ixf = (gx  + 1.0f) * ((WP - 1) * 0.5f);
    float iyf = (gyv + 1.0f) * ((HP - 1) * 0.5f);

    float x0f = floorf(ixf);
    float y0f = floorf(iyf);
    float wx  = ixf - x0f;
    float wy  = iyf - y0f;
    int   x0  = (int)x0f;
    int   y0  = (int)y0f;

    y0 = min(max(y0, 0), HP - 2);
    if (x0 < 0)      { x0 = 0;      wx = 0.0f; }
    if (x0 > WP - 2) { x0 = WP - 2; wx = 1.0f; }

    float wxm = 1.0f - wx, wym = 1.0f - wy;
    const float w00 = wxm * wym;
    const float w01 = wx  * wym;
    const float w10 = wxm * wy;
    const float w11 = wx  * wy;

    // ---- block-wide min/max of (x0, y0) ----
    int xmn = x0, xmx = x0, ymn = y0, ymx = y0;
    #pragma unroll
    for (int o = 16; o; o >>= 1) {
        xmn = min(xmn, __shfl_xor_sync(0xffffffffu, xmn, o));
        xmx = max(xmx, __shfl_xor_sync(0xffffffffu, xmx, o));
        ymn = min(ymn, __shfl_xor_sync(0xffffffffu, ymn, o));
        ymx = max(ymx, __shfl_xor_sync(0xffffffffu, ymx, o));
    }
    if (lane == 0) {
        sred[warp]      = xmn;
        sred[8 + warp]  = xmx;
        sred[16 + warp] = ymn;
        sred[24 + warp] = ymx;
    }
    __syncthreads();
    xmn = sred[0]; xmx = sred[8]; ymn = sred[16]; ymx = sred[24];
    #pragma unroll
    for (int i = 1; i < 8; ++i) {
        xmn = min(xmn, sred[i]);
        xmx = max(xmx, sred[8 + i]);
        ymn = min(ymn, sred[16 + i]);
        ymx = max(ymx, sred[24 + i]);
    }
    const int W     = xmx + 2 - xmn;   // columns needed (incl. +1 tap)
    const int nrows = ymx + 2 - ymn;   // rows needed

    const size_t obase = ((size_t)b * CC) * HW + (size_t)y * WW + x;

    if (W <= PW && nrows <= PH) {
        // ================= main path: smem patch gather =================
        // (all pixels provably mapped: unmapped => r<16.3 => W>>PW)
        const unsigned nrw   = (unsigned)(nrows * W);
        const unsigned total = (unsigned)GC * nrw;           // <= 4896
        const float*   pb    = polar + (size_t)b * CC * PLANE
                             + (size_t)ymn * WP + xmn;
        const int      lb    = (y0 - ymn) * PW + (x0 - xmn);
        float*         sps   = (float*)sp;

        for (int g = 0; g < NGRP; ++g) {
            const float* ps = pb + (size_t)(g * GC) * PLANE;
            // flattened, coalesced staging: px fastest within flat index
            for (unsigned k = tid; k < total; k += 256) {
                unsigned c   = k / nrw;
                unsigned rem = k - c * nrw;
                unsigned py  = rem / (unsigned)W;
                unsigned px  = rem - py * (unsigned)W;
                float v = __ldg(ps + (size_t)c * PLANE + py * WP + px);
                // channel-pair interleaved: sp[pair][py][px].{x=even,y=odd}
                sps[(((c >> 1) * PH + py) * PW + px) * 2 + (c & 1)] = v;
            }
            __syncthreads();

            float* o = out + obase + (size_t)(g * GC) * HW;
            #pragma unroll
            for (int p = 0; p < GC / 2; ++p) {
                const float2* t = sp + p * (PH * PW) + lb;
                float2 v00 = t[0];
                float2 v01 = t[1];
                float2 v10 = t[PW];
                float2 v11 = t[PW + 1];
                float r0 = v00.x * w00 + v01.x * w01 + v10.x * w10 + v11.x * w11;
                float r1 = v00.y * w00 + v01.y * w01 + v10.y * w10 + v11.y * w11;
                __stcs(o + (size_t)(2 * p)     * HW, r0);
                __stcs(o + (size_t)(2 * p + 1) * HW, r1);
            }
            __syncthreads();
        }
    } else {
        // ============== fallback: direct gather (center/seam) ==========
        float* o = out + obase;
        if (mapped) {
            const float* pp = polar + (size_t)b * CC * PLANE
                            + (size_t)y0 * WP + x0;
            #pragma unroll 4
            for (int c = 0; c < CC; ++c) {
                float v00 = __ldg(pp);
                float v01 = __ldg(pp + 1);
                float v10 = __ldg(pp + WP);
                float v11 = __ldg(pp + WP + 1);
                __stcs(o, v00 * w00 + v01 * w01 + v10 * w10 + v11 * w11);
                pp += PLANE;
                o  += HW;
            }
        } else {
            const float* r = ref + obase;
            #pragma unroll 8
            for (int c = 0; c < CC; ++c) {
                __stcs(o, __ldg(r));
                r += HW;
                o += HW;
            }
        }
    }
}

extern "C" void kernel_launch(void* const* d_in, const int* in_sizes, int n_in,
                              void* d_out, int out_size) {
    const float* polar = (const float*)d_in[0];   // [B,C,HP,WP]
    const float* ref   = (const float*)d_in[1];   // [B,C,H,W]
    float*       out   = (float*)d_out;           // [B,C,H,W]

    dim3 grid(WW / 32, HH / 8, BB);   // (16, 64, 4) = 4096 blocks
    k_fused<<<grid, 256>>>(polar, ref, out);
}

// round 13
// speedup vs baseline: 1.8034x; 1.6480x over previous
#include <cuda_runtime.h>
#include <cuda_fp16.h>
#include <math.h>

// Problem constants (fixed by the reference)
#define HH 512
#define WW 512
#define HP 64
#define WP 2048
#define BB 4
#define CC 64
#define HW (HH * WW)          // 262144 cart pixels per plane
#define PLANE (HP * WP)       // 131072 polar elements per plane

// fp16 channel-last mirror of polar: half index ((b*HP+y)*WP + x)*CC + c.
// Declared as uint4 for 16B alignment. 4*64*2048*64 halves = 64 MiB.
#define PT_U4 ((size_t)BB * HP * WP * CC / 8)
__device__ uint4 g_pt[PT_U4];

// ======================= Kernel A: convert + transpose ======================
// Grid (WP/128, HP*BB). Block 256. Reads polar[b][c][y][X0..X0+127],
// writes channel-last fp16 chunks.
__global__ void __launch_bounds__(256)
k_transpose(const float* __restrict__ polar) {
    __shared__ float sA[CC][129];
    const int tid = threadIdx.x;
    const int X0  = blockIdx.x << 7;
    const int y   = blockIdx.y & 63;
    const int b   = blockIdx.y >> 6;

    const float* src = polar + (size_t)b * CC * PLANE + (size_t)y * WP + X0;
    {
        const int x  = tid & 127;
        const int c2 = tid >> 7;          // 0..1
        #pragma unroll
        for (int i = 0; i < 32; ++i) {
            int c = 2 * i + c2;
            sA[c][x] = __ldg(src + (size_t)c * PLANE + x);
        }
    }
    __syncthreads();

    __half* dst = (__half*)g_pt + ((size_t)(b * HP + y) * WP + X0) * CC;
    {
        const int c8 = tid & 7;           // 8-channel chunk
        const int xl = tid >> 3;          // 0..31
        #pragma unroll
        for (int p = 0; p < 4; ++p) {
            int x = xl + (p << 5);
            __half2 h[4];
            #pragma unroll
            for (int j = 0; j < 4; ++j)
                h[j] = __floats2half2_rn(sA[c8 * 8 + 2 * j][x],
                                         sA[c8 * 8 + 2 * j + 1][x]);
            *(uint4*)(dst + (size_t)x * CC + c8 * 8) = *(uint4*)h;
        }
    }
}

// =========================== Kernel B: gather ==============================
__device__ __forceinline__ float4 h4_to_f4(uint2 u) {
    __half2 h0 = *reinterpret_cast<__half2*>(&u.x);
    __half2 h1 = *reinterpret_cast<__half2*>(&u.y);
    float2 f0 = __half22float2(h0);
    float2 f1 = __half22float2(h1);
    return make_float4(f0.x, f0.y, f1.x, f1.y);
}

// Block 256 = 32(x) x 8(y) cart tile for one b. Per row: warp handles
// 2 px with 16 lanes each (lane = 4 channels, LDG.64 per tap = one quarter
// of a 128B channel-chunk). Stores recoalesced through smem.
__global__ void __launch_bounds__(256, 8)
k_gather(const float* __restrict__ ref,
         float*       __restrict__ out) {
    __shared__ float  sout[CC][33];
    __shared__ int    spk[256];
    __shared__ float4 sw[256];

    const int tid  = threadIdx.x;
    const int lane = tid & 31;
    const int warp = tid >> 5;

    const int X0 = blockIdx.x << 5;
    const int Y0 = blockIdx.y << 3;
    const int b  = blockIdx.z;

    // ---- per-thread pixel map (proven analytic chain, bitwise mask) ----
    {
        const int xloc = tid & 31;
        const int yloc = tid >> 5;
        const int x = X0 + xloc;
        const int y = Y0 + yloc;

        const float c1  = 362.03867196751236f;       // f32(256*sqrt(2))
        const float PIf = 3.14159265358979323846f;   // f32(np.pi)

        const float yyc = ((float)y - 256.0f) + 0.5f;
        const float xxc = ((float)x - 256.0f) + 0.5f;

        float d2    = __fadd_rn(__fmul_rn(xxc, xxc), __fmul_rn(yyc, yyc));
        float depth = __fsqrt_rn(d2);
        float index_y = __fsub_rn(__fmul_rn(__fdiv_rn(depth, c1), 67.0f), 3.0f);
        const bool mapped = (index_y > 0.0f);

        float phi     = PIf - atan2f(yyc, xxc);
        float index_x = phi / PIf / 2.0f * (float)WP;
        float gx  = index_x / (float)WP * 2.0f - 1.0f;
        float gyv = -(index_y / (float)HP * 2.0f - 1.0f);
        float ixf = (gx  + 1.0f) * ((WP - 1) * 0.5f);
        float iyf = (gyv + 1.0f) * ((HP - 1) * 0.5f);

        float x0f = floorf(ixf);
        float y0f = floorf(iyf);
        float wx  = ixf - x0f;
        float wy  = iyf - y0f;
        int   x0  = (int)x0f;
        int   y0  = (int)y0f;

        y0 = min(max(y0, 0), HP - 2);
        if (x0 < 0)      { x0 = 0;      wx = 0.0f; }
        if (x0 > WP - 2) { x0 = WP - 2; wx = 1.0f; }

        float wxm = 1.0f - wx, wym = 1.0f - wy;
        spk[tid] = mapped ? (y0 * WP + x0) : -1;
        sw[tid]  = make_float4(wxm * wym, wx * wym, wxm * wy, wx * wy);
    }
    __syncthreads();

    const __half* ptb = (const __half*)g_pt + (size_t)b * HP * WP * CC;
    const int c4   = lane & 15;          // which 4-channel group
    const int psel = lane >> 4;          // which of the 2 px

    for (int r = 0; r < 8; ++r) {
        const int y = Y0 + r;

        // ---- gather phase: 8 warps x 2 rounds cover 32 px, all 64 ch ----
        #pragma unroll
        for (int t = 0; t < 2; ++t) {
            const int pxl  = ((warp + (t << 3)) << 1) + psel;   // 0..31
            const int pidx = (r << 5) + pxl;
            const int pk   = spk[pidx];
            const float4 w4 = sw[pidx];
            float4 acc;

            if (pk >= 0) {
                const __half* base = ptb + ((size_t)pk << 6) + (c4 << 2);
                uint2 u00 = __ldg((const uint2*)(base));
                uint2 u01 = __ldg((const uint2*)(base + CC));
                uint2 u10 = __ldg((const uint2*)(base + WP * CC));
                uint2 u11 = __ldg((const uint2*)(base + WP * CC + CC));
                float4 f00 = h4_to_f4(u00);
                float4 f01 = h4_to_f4(u01);
                float4 f10 = h4_to_f4(u10);
                float4 f11 = h4_to_f4(u11);
                acc.x = f00.x * w4.x + f01.x * w4.y + f10.x * w4.z + f11.x * w4.w;
                acc.y = f00.y * w4.x + f01.y * w4.y + f10.y * w4.z + f11.y * w4.w;
                acc.z = f00.z * w4.x + f01.z * w4.y + f10.z * w4.z + f11.z * w4.w;
                acc.w = f00.w * w4.x + f01.w * w4.y + f10.w * w4.z + f11.w * w4.w;
            } else {
                // unmapped (center disk, ~0.3% of px): pass through ref
                const float* rp = ref + (size_t)b * CC * HW
                                + (size_t)(c4 << 2) * HW
                                + (size_t)y * WW + (X0 + pxl);
                acc.x = __ldg(rp);
                acc.y = __ldg(rp + HW);
                acc.z = __ldg(rp + 2 * HW);
                acc.w = __ldg(rp + 3 * HW);
            }
            const int cb = c4 << 2;
            sout[cb + 0][pxl] = acc.x;
            sout[cb + 1][pxl] = acc.y;
            sout[cb + 2][pxl] = acc.z;
            sout[cb + 3][pxl] = acc.w;
        }
        __syncthreads();

        // ---- store phase: 128B coalesced rows, evict-first ----
        {
            const int xs = tid & 31;
            const int c0 = tid >> 5;
            #pragma unroll
            for (int p = 0; p < 8; ++p) {
                int c = c0 + (p << 3);
                __stcs(out + (size_t)b * CC * HW + (size_t)c * HW
                           + (size_t)y * WW + X0 + xs,
                       sout[c][xs]);
            }
        }
        __syncthreads();
    }
}

extern "C" void kernel_launch(void* const* d_in, const int* in_sizes, int n_in,
                              void* d_out, int out_size) {
    const float* polar = (const float*)d_in[0];   // [B,C,HP,WP]
    const float* ref   = (const float*)d_in[1];   // [B,C,H,W]
    float*       out   = (float*)d_out;           // [B,C,H,W]

    dim3 gA(WP / 128, HP * BB);        // (16, 256)
    k_transpose<<<gA, 256>>>(polar);

    dim3 gB(WW / 32, HH / 8, BB);      // (16, 64, 4)
    k_gather<<<gB, 256>>>(ref, out);
}

// round 17
// speedup vs baseline: 2.1384x; 1.1857x over previous
#include <cuda_runtime.h>
#include <cuda_fp16.h>
#include <math.h>

// Problem constants (fixed by the reference)
#define HH 512
#define WW 512
#define HP 64
#define WP 2048
#define BB 4
#define CC 64
#define HW (HH * WW)          // 262144 cart pixels per plane
#define PLANE (HP * WP)       // 131072 polar elements per plane

// fp16 channel-last mirror of polar: half index ((b*HP+y)*WP + x)*CC + c.
#define PT_U4 ((size_t)BB * HP * WP * CC / 8)
__device__ uint4 g_pt[PT_U4];

// ======================= Kernel A: convert + transpose ======================
// Grid (WP/128, HP*BB). Block 256. Vectorized LDG.128 reads, XOR-swizzled
// float4 smem tile (conflict-free both phases), STG.128 fp16 chunk writes.
__global__ void __launch_bounds__(256)
k_transpose(const float* __restrict__ polar) {
    __shared__ float4 sA[CC * 33];     // 33 f4-slots per channel row, swizzled
    const int tid = threadIdx.x;
    const int X0  = blockIdx.x << 7;
    const int y   = blockIdx.y & 63;
    const int b   = blockIdx.y >> 6;

    const float* src = polar + (size_t)b * CC * PLANE + (size_t)y * WP + X0;

    // read phase: 2048 float4, 8 per thread, fully coalesced
    #pragma unroll
    for (int i = 0; i < 8; ++i) {
        int k  = i * 256 + tid;
        int c  = k >> 5;                       // channel (warp-uniform)
        int x4 = k & 31;                       // f4 column
        float4 v = __ldg((const float4*)(src + (size_t)c * PLANE) + x4);
        sA[c * 33 + (x4 ^ ((c >> 3) & 7))] = v;   // swizzled slot
    }
    __syncthreads();

    // pack phase: thread = (c8 = tid&7, x = (tid>>3) + 32p), 8 ch -> uint4
    __half* dst = (__half*)g_pt + ((size_t)(b * HP + y) * WP + X0) * CC;
    const int c8 = tid & 7;
    const int xb = tid >> 3;                   // 0..31
    const float* sAf = (const float*)sA;
    #pragma unroll
    for (int p = 0; p < 4; ++p) {
        int x   = xb + (p << 5);               // 0..127
        int xq  = x >> 2;                      // f4 column of x
        int xl  = x & 3;
        __half2 h[4];
        #pragma unroll
        for (int j = 0; j < 4; ++j) {
            int c0 = c8 * 8 + 2 * j;
            float f0 = sAf[(c0 * 33 + (xq ^ c8)) * 4 + xl];
            float f1 = sAf[((c0 + 1) * 33 + (xq ^ c8)) * 4 + xl];
            h[j] = __floats2half2_rn(f0, f1);
        }
        *(uint4*)(dst + (size_t)x * CC + c8 * 8) = *(uint4*)h;
    }
}

// =========================== Kernel B: gather ==============================
__device__ __forceinline__ void u4_taps_fma(uint4 u, float w, float* acc) {
    const __half2* h = (const __half2*)&u;
    #pragma unroll
    for (int i = 0; i < 4; ++i) {
        float2 f = __half22float2(h[i]);
        acc[2 * i]     += f.x * w;
        acc[2 * i + 1] += f.y * w;
    }
}

// Block 256 = 32(x) x 8(y) cart tile. Gather: warp = 4 px, lane = 8 channels
// (LDG.128 per tap = quarter of a 128B channel chunk). Results go to smem as
// fp16 (cheap transpose), flushed as coalesced fp32 rows. Double-buffered,
// one barrier per row.
__global__ void __launch_bounds__(256, 6)
k_gather(const float* __restrict__ ref,
         float*       __restrict__ out) {
    __shared__ __half sH[2][32 * 68];          // [buf][px*68 + c], 68 = 64+pad
    __shared__ int    spk[256];
    __shared__ float4 sw[256];

    const int tid  = threadIdx.x;
    const int lane = tid & 31;
    const int warp = tid >> 5;

    const int X0 = blockIdx.x << 5;
    const int Y0 = blockIdx.y << 3;
    const int b  = blockIdx.z;

    // ---- per-thread pixel map (proven analytic chain, bitwise mask) ----
    {
        const int x = X0 + (tid & 31);
        const int y = Y0 + (tid >> 5);

        const float c1  = 362.03867196751236f;       // f32(256*sqrt(2))
        const float PIf = 3.14159265358979323846f;   // f32(np.pi)

        const float yyc = ((float)y - 256.0f) + 0.5f;
        const float xxc = ((float)x - 256.0f) + 0.5f;

        float d2    = __fadd_rn(__fmul_rn(xxc, xxc), __fmul_rn(yyc, yyc));
        float depth = __fsqrt_rn(d2);
        float index_y = __fsub_rn(__fmul_rn(__fdiv_rn(depth, c1), 67.0f), 3.0f);
        const bool mapped = (index_y > 0.0f);

        float phi     = PIf - atan2f(yyc, xxc);
        float index_x = phi / PIf / 2.0f * (float)WP;
        float gx  = index_x / (float)WP * 2.0f - 1.0f;
        float gyv = -(index_y / (float)HP * 2.0f - 1.0f);
        float ixf = (gx  + 1.0f) * ((WP - 1) * 0.5f);
        float iyf = (gyv + 1.0f) * ((HP - 1) * 0.5f);

        float x0f = floorf(ixf);
        float y0f = floorf(iyf);
        float wx  = ixf - x0f;
        float wy  = iyf - y0f;
        int   x0  = (int)x0f;
        int   y0  = (int)y0f;

        y0 = min(max(y0, 0), HP - 2);
        if (x0 < 0)      { x0 = 0;      wx = 0.0f; }
        if (x0 > WP - 2) { x0 = WP - 2; wx = 1.0f; }

        float wxm = 1.0f - wx, wym = 1.0f - wy;
        spk[tid] = mapped ? (y0 * WP + x0) : -1;
        sw[tid]  = make_float4(wxm * wym, wx * wym, wxm * wy, wx * wy);
    }

    const __half* ptb = (const __half*)g_pt + (size_t)b * HP * WP * CC;
    const int c8  = lane & 7;                  // channel octet
    const int pxl = (warp << 2) + (lane >> 3); // pixel 0..31 (fixed)

    // ---- gather one row into sH[buf] ----
    auto stage = [&](int r, int buf) {
        const int    pidx = (r << 5) + pxl;
        const int    pk   = spk[pidx];
        const float4 w4   = sw[pidx];
        float acc[8] = {0, 0, 0, 0, 0, 0, 0, 0};

        if (pk >= 0) {
            const __half* base = ptb + ((size_t)pk << 6) + (c8 << 3);
            uint4 u00 = __ldg((const uint4*)(base));
            uint4 u01 = __ldg((const uint4*)(base + CC));
            uint4 u10 = __ldg((const uint4*)(base + WP * CC));
            uint4 u11 = __ldg((const uint4*)(base + WP * CC + CC));
            u4_taps_fma(u00, w4.x, acc);
            u4_taps_fma(u01, w4.y, acc);
            u4_taps_fma(u10, w4.z, acc);
            u4_taps_fma(u11, w4.w, acc);
        } else {
            // unmapped (center disk, rare): pass through ref
            const float* rp = ref + ((size_t)b * CC + (c8 << 3)) * HW
                            + (size_t)(Y0 + r) * WW + X0 + pxl;
            #pragma unroll
            for (int j = 0; j < 8; ++j) acc[j] = __ldg(rp + (size_t)j * HW);
        }

        __half2 h[4];
        #pragma unroll
        for (int i = 0; i < 4; ++i)
            h[i] = __floats2half2_rn(acc[2 * i], acc[2 * i + 1]);
        // px stride 68 halves = 136B (8B-aligned chunks, conflict-free)
        uint2* sd = (uint2*)(&sH[buf][pxl * 68 + (c8 << 3)]);
        sd[0] = make_uint2(*(uint*)&h[0], *(uint*)&h[1]);
        sd[1] = make_uint2(*(uint*)&h[2], *(uint*)&h[3]);
    };

    // ---- flush one row: fp16 -> fp32, coalesced streaming stores ----
    auto flush = [&](int r, int buf) {
        const uint* sHw = (const uint*)sH[buf];
        #pragma unroll
        for (int q = 0; q < 4; ++q) {
            int idx = q * 256 + tid;
            int c2  = idx >> 5;                // channel pair 0..31
            int xs  = idx & 31;
            uint w = sHw[xs * 34 + c2];
            float2 f = __half22float2(*(__half2*)&w);
            float* o = out + ((size_t)b * CC + 2 * c2) * HW
                     + (size_t)(Y0 + r) * WW + X0 + xs;
            __stcs(o, f.x);
            __stcs(o + HW, f.y);
        }
    };

    __syncthreads();          // spk/sw ready
    stage(0, 0);
    __syncthreads();
    #pragma unroll
    for (int r = 0; r < 7; ++r) {
        stage(r + 1, (r + 1) & 1);
        flush(r, r & 1);
        __syncthreads();
    }
    flush(7, 1);
}

extern "C" void kernel_launch(void* const* d_in, const int* in_sizes, int n_in,
                              void* d_out, int out_size) {
    const float* polar = (const float*)d_in[0];   // [B,C,HP,WP]
    const float* ref   = (const float*)d_in[1];   // [B,C,H,W]
    float*       out   = (float*)d_out;           // [B,C,H,W]

    dim3 gA(WP / 128, HP * BB);        // (16, 256)
    k_transpose<<<gA, 256>>>(polar);

    dim3 gB(WW / 32, HH / 8, BB);      // (16, 64, 4)
    k_gather<<<gB, 256>>>(ref, out);
}